// round 4
// baseline (speedup 1.0000x reference)
#include <cuda_runtime.h>

#define NB   48
#define CHN  3
#define HH   256
#define WW   256
#define NIC  (NB*CHN)
#define NPIX (HH*WW)

#define TW 32
#define TH 32
#define IW 42
#define IH 42

__device__ double g_acc;
__device__ unsigned char g_wbonus[NB * NPIX];   // 3*m0 + 3*m1 + 2*m2, in [0,8]

// Normalized 1D Gaussian, k=11, sigma=1.5 (matches jnp to ~1e-6 rel)
__device__ constexpr float G[11] = {
    0.00102838f, 0.00759876f, 0.03600078f, 0.10936071f, 0.21300554f,
    0.26601172f,
    0.21300554f, 0.10936071f, 0.03600078f, 0.00759876f, 0.00102838f
};

__global__ void zero_kernel() { g_acc = 0.0; }

// One block per (row h, image n). Per-row edge thresholds computed once by
// thread 0; per-pixel work is 24 compares.
__global__ void __launch_bounds__(WW) wmap_kernel(const float* __restrict__ lmk) {
    int h = blockIdx.x;
    int n = blockIdx.y;
    int w = threadIdx.x;

    __shared__ float tthr[24];
    __shared__ int   ycnd[24];
    __shared__ float bxmin[3], bxmax[3];
    __shared__ int   rowok[3];

    if (w == 0) {
        const float* L = lmk + n * 136;
        float Y = (float)h;
        const int starts[3] = {36, 42, 48};
        const int cnts[3]   = {6, 6, 12};
        int e = 0;
        for (int p = 0; p < 3; p++) {
            int s = starts[p], cn = cnts[p];
            float mnx = 1e30f, mxx = -1e30f, mny = 1e30f, mxy = -1e30f;
            for (int i = 0; i < cn; i++) {
                float x = L[2*(s+i)], y = L[2*(s+i)+1];
                mnx = fminf(mnx, x); mxx = fmaxf(mxx, x);
                mny = fminf(mny, y); mxy = fmaxf(mxy, y);
            }
            float fxmin = floorf(mnx), fxmax = floorf(mxx);
            float fymin = floorf(mny), fymax = floorf(mxy);
            bool valid = (fxmin >= 0.f) && (fymin >= 0.f) &&
                         (fxmax < (float)WW) && (fymax < (float)HH);
            rowok[p] = (valid && (Y >= fymin) && (Y < fymax)) ? 1 : 0;
            bxmin[p] = fxmin; bxmax[p] = fxmax;
            for (int i = 0; i < cn; i++) {
                int j = (i + 1 == cn) ? 0 : i + 1;
                float x1 = L[2*(s+i)], y1 = L[2*(s+i)+1];
                float x2 = L[2*(s+j)], y2 = L[2*(s+j)+1];
                ycnd[e] = ((y1 > Y) != (y2 > Y)) ? 1 : 0;
                tthr[e] = (x2 - x1) * (Y - y1) / (y2 - y1 + 1e-6f) + x1;
                e++;
            }
        }
    }
    __syncthreads();

    float X = (float)w;
    int c0 = 0, c1 = 0, c2 = 0;
    #pragma unroll
    for (int e = 0; e < 6; e++)  c0 += (ycnd[e]      && (X < tthr[e]))      ? 1 : 0;
    #pragma unroll
    for (int e = 0; e < 6; e++)  c1 += (ycnd[6 + e]  && (X < tthr[6 + e]))  ? 1 : 0;
    #pragma unroll
    for (int e = 0; e < 12; e++) c2 += (ycnd[12 + e] && (X < tthr[12 + e])) ? 1 : 0;

    int m0 = (rowok[0] && (c0 & 1) && (X >= bxmin[0]) && (X < bxmax[0])) ? 1 : 0;
    int m1 = (rowok[1] && (c1 & 1) && (X >= bxmin[1]) && (X < bxmax[1])) ? 1 : 0;
    int m2 = (rowok[2] && (c2 & 1) && (X >= bxmin[2]) && (X < bxmax[2])) ? 1 : 0;

    g_wbonus[n * NPIX + h * WW + w] = (unsigned char)(3*m0 + 3*m1 + 2*m2);
}

// Fused: load 42x42 halo tile of (x,y); separable 11-tap Gaussian of
// (x, y, x^2, y^2, xy); dssim + l1 + weighted-l1; block reduce; one atomic.
__global__ void __launch_bounds__(256) main_kernel(const float* __restrict__ pred,
                                                   const float* __restrict__ target) {
    __shared__ float2 sP [IH][IW];   // (x, y)
    __shared__ float2 hMU[IH][TW];   // row-conv of (x, y)
    __shared__ float2 hSQ[IH][TW];   // row-conv of (x^2, y^2)
    __shared__ float  hE [IH][TW];   // row-conv of (x*y)
    __shared__ float  red[8];

    const int tid  = threadIdx.x;
    const int tile = blockIdx.x;     // 0..63
    const int ic   = blockIdx.y;     // 0..143
    const int ty = tile >> 3, tx = tile & 7;
    const int h0 = ty * TH, w0 = tx * TW;
    const int n  = ic / CHN;

    const float* xp = pred   + ic * NPIX;
    const float* yp = target + ic * NPIX;

    // Phase 1: load halo tile with SAME zero padding
    for (int i = tid; i < IH * IW; i += 256) {
        int r = i / IW, q = i - r * IW;
        int gh = h0 - 5 + r, gw = w0 - 5 + q;
        float xv = 0.f, yv = 0.f;
        if (gh >= 0 && gh < HH && gw >= 0 && gw < WW) {
            int off = gh * WW + gw;
            xv = xp[off]; yv = yp[off];
        }
        sP[r][q] = make_float2(xv, yv);
    }
    __syncthreads();

    // Phase 2: horizontal pass, 4-wide register blocking (42 rows x 8 groups)
    for (int item = tid; item < IH * 8; item += 256) {
        int r  = item >> 3;
        int g4 = (item & 7) << 2;
        float amux[4] = {0,0,0,0}, amuy[4] = {0,0,0,0};
        float asqx[4] = {0,0,0,0}, asqy[4] = {0,0,0,0};
        float ae  [4] = {0,0,0,0};
        #pragma unroll
        for (int k = 0; k < 14; k++) {
            float2 p = sP[r][g4 + k];
            float qx = p.x * p.x, qy = p.y * p.y, ee = p.x * p.y;
            #pragma unroll
            for (int o = 0; o < 4; o++) {
                int t = k - o;
                if (t >= 0 && t < 11) {
                    float gg = G[t];
                    amux[o] += gg * p.x;  amuy[o] += gg * p.y;
                    asqx[o] += gg * qx;   asqy[o] += gg * qy;
                    ae[o]   += gg * ee;
                }
            }
        }
        #pragma unroll
        for (int o = 0; o < 4; o++) {
            hMU[r][g4 + o] = make_float2(amux[o], amuy[o]);
            hSQ[r][g4 + o] = make_float2(asqx[o], asqy[o]);
            hE [r][g4 + o] = ae[o];
        }
    }
    __syncthreads();

    // Phase 3: vertical pass (4-row blocking) + dssim + L1 terms
    const int col = tid & 31;
    const int rg  = tid >> 5;       // row group: local rows 4*rg .. 4*rg+3

    float amux[4] = {0,0,0,0}, amuy[4] = {0,0,0,0};
    float asqx[4] = {0,0,0,0}, asqy[4] = {0,0,0,0};
    float ae  [4] = {0,0,0,0};
    #pragma unroll
    for (int k = 0; k < 14; k++) {
        int rr = 4 * rg + k;
        float2 mu = hMU[rr][col];
        float2 sq = hSQ[rr][col];
        float  ee = hE [rr][col];
        #pragma unroll
        for (int o = 0; o < 4; o++) {
            int t = k - o;
            if (t >= 0 && t < 11) {
                float gg = G[t];
                amux[o] += gg * mu.x;  amuy[o] += gg * mu.y;
                asqx[o] += gg * sq.x;  asqy[o] += gg * sq.y;
                ae[o]   += gg * ee;
            }
        }
    }

    const float C1 = 0.01f * 0.01f;
    const float C2 = 0.03f * 0.03f;
    const unsigned char* wb = g_wbonus + n * NPIX;

    float lsum = 0.f;
    #pragma unroll
    for (int o = 0; o < 4; o++) {
        int lr = 4 * rg + o;
        float mux = amux[o], muy = amuy[o];
        float sx  = asqx[o] - mux * mux;
        float sy  = asqy[o] - muy * muy;
        float sxy = ae[o]   - mux * muy;
        float num = (2.f * mux * muy + C1) * (2.f * sxy + C2);
        float den = (mux * mux + muy * muy + C1) * (sx + sy + C2);
        float ssim  = num / (den + 1e-8f);
        float dssim = 0.5f * (1.f - ssim);

        float2 p = sP[lr + 5][col + 5];
        float ad = fabsf(p.x - p.y);
        float bonus = (float)wb[(h0 + lr) * WW + (w0 + col)];

        // 10*dssim + 10*ad + 5*w*ad,  w = 1 + bonus  ->  (15 + 5*bonus)*ad
        lsum += 10.f * dssim + (15.f + 5.f * bonus) * ad;
    }

    // Warp shuffle reduction, then one cross-warp pass -> one double atomic
    #pragma unroll
    for (int s = 16; s > 0; s >>= 1)
        lsum += __shfl_xor_sync(0xFFFFFFFFu, lsum, s);
    if (col == 0) red[rg] = lsum;
    __syncthreads();
    if (tid == 0) {
        float t = red[0] + red[1] + red[2] + red[3]
                + red[4] + red[5] + red[6] + red[7];
        atomicAdd(&g_acc, (double)t);
    }
}

__global__ void fin_kernel(float* __restrict__ out) {
    out[0] = (float)(g_acc * (1.0 / (double)(NB * CHN * NPIX)));
}

extern "C" void kernel_launch(void* const* d_in, const int* in_sizes, int n_in,
                              void* d_out, int out_size) {
    (void)in_sizes; (void)n_in; (void)out_size;
    const float* pred   = (const float*)d_in[0];
    const float* target = (const float*)d_in[1];
    const float* lmk    = (const float*)d_in[2];
    float* out = (float*)d_out;

    zero_kernel<<<1, 1>>>();
    wmap_kernel<<<dim3(HH, NB), WW>>>(lmk);
    main_kernel<<<dim3(64, NIC), 256>>>(pred, target);
    fin_kernel<<<1, 1>>>(out);
}

// round 5
// speedup vs baseline: 1.3602x; 1.3602x over previous
#include <cuda_runtime.h>

#define NB   48
#define CHN  3
#define HH   256
#define WW   256
#define NIC  (NB*CHN)
#define NPIX (HH*WW)

#define TH   32
#define TW   64
#define IHH  42           // TH + 10
#define IWW  74           // TW + 10
#define XP   75           // X/Y plane stride (odd bank stride -> conflict-free)
#define VP   77           // V plane stride (77 mod 32 = 13, odd -> conflict-free)

#define SM_FLOATS (2*IHH*XP + 5*TH*VP + 8)
#define SM_BYTES  (SM_FLOATS * 4)

__device__ double g_acc;
__device__ unsigned char g_wbonus[NB * NPIX];   // 3*m0 + 3*m1 + 2*m2 in [0,8]

// Normalized 1D Gaussian, k=11, sigma=1.5
__device__ constexpr float G[11] = {
    0.00102838f, 0.00759876f, 0.03600078f, 0.10936071f, 0.21300554f,
    0.26601172f,
    0.21300554f, 0.10936071f, 0.03600078f, 0.00759876f, 0.00102838f
};

// One block per (row h, image n). Edge thresholds computed in parallel by
// lanes 0..23 (one edge each); bbox/validity by lanes 24..26.
__global__ void __launch_bounds__(WW) wmap_kernel(const float* __restrict__ lmk) {
    int h = blockIdx.x;
    int n = blockIdx.y;
    int w = threadIdx.x;

    __shared__ float tthr[24];
    __shared__ int   ycnd[24];
    __shared__ float bxmin[3], bxmax[3];
    __shared__ int   rowok[3];

    if (h == 0 && n == 0 && w == 255) g_acc = 0.0;   // fold zero_kernel in

    const float* L = lmk + n * 136;
    float Y = (float)h;

    if (w < 24) {
        int p    = (w < 6) ? 0 : ((w < 12) ? 1 : 2);
        int base = (p == 0) ? 36 : ((p == 1) ? 42 : 48);
        int cnt  = (p == 2) ? 12 : 6;
        int i    = w - ((p == 0) ? 0 : ((p == 1) ? 6 : 12));
        int j    = (i + 1 == cnt) ? 0 : i + 1;
        float x1 = L[2*(base+i)],   y1 = L[2*(base+i)+1];
        float x2 = L[2*(base+j)],   y2 = L[2*(base+j)+1];
        ycnd[w] = ((y1 > Y) != (y2 > Y)) ? 1 : 0;
        tthr[w] = (x2 - x1) * (Y - y1) / (y2 - y1 + 1e-6f) + x1;
    } else if (w < 27) {
        int p    = w - 24;
        int base = (p == 0) ? 36 : ((p == 1) ? 42 : 48);
        int cnt  = (p == 2) ? 12 : 6;
        float mnx = 1e30f, mxx = -1e30f, mny = 1e30f, mxy = -1e30f;
        for (int i = 0; i < cnt; i++) {
            float x = L[2*(base+i)], y = L[2*(base+i)+1];
            mnx = fminf(mnx, x); mxx = fmaxf(mxx, x);
            mny = fminf(mny, y); mxy = fmaxf(mxy, y);
        }
        float fxmin = floorf(mnx), fxmax = floorf(mxx);
        float fymin = floorf(mny), fymax = floorf(mxy);
        bool valid = (fxmin >= 0.f) && (fymin >= 0.f) &&
                     (fxmax < (float)WW) && (fymax < (float)HH);
        rowok[p] = (valid && (Y >= fymin) && (Y < fymax)) ? 1 : 0;
        bxmin[p] = fxmin; bxmax[p] = fxmax;
    }
    __syncthreads();

    float X = (float)w;
    int c0 = 0, c1 = 0, c2 = 0;
    #pragma unroll
    for (int e = 0; e < 6; e++)  c0 += (ycnd[e]      && (X < tthr[e]))      ? 1 : 0;
    #pragma unroll
    for (int e = 0; e < 6; e++)  c1 += (ycnd[6 + e]  && (X < tthr[6 + e]))  ? 1 : 0;
    #pragma unroll
    for (int e = 0; e < 12; e++) c2 += (ycnd[12 + e] && (X < tthr[12 + e])) ? 1 : 0;

    int m0 = (rowok[0] && (c0 & 1) && (X >= bxmin[0]) && (X < bxmax[0])) ? 1 : 0;
    int m1 = (rowok[1] && (c1 & 1) && (X >= bxmin[1]) && (X < bxmax[1])) ? 1 : 0;
    int m2 = (rowok[2] && (c2 & 1) && (X >= bxmin[2]) && (X < bxmax[2])) ? 1 : 0;

    g_wbonus[n * NPIX + h * WW + w] = (unsigned char)(3*m0 + 3*m1 + 2*m2);
}

// Fused main: 32x64 tile. Phase1 loads halo (and folds in L1 terms),
// PhaseV vertical 11-tap conv of 5 fields (8-row register blocking),
// PhaseH horizontal conv (8-col blocking, 256 items exactly) + dssim.
__global__ void __launch_bounds__(256, 3) main_kernel(const float* __restrict__ pred,
                                                      const float* __restrict__ target) {
    extern __shared__ float sm[];
    float* Xp  = sm;                       // [IHH][XP]
    float* Yp  = sm +   IHH*XP;            // [IHH][XP]
    float* Vb  = sm + 2*IHH*XP;            // 5 planes [TH][VP]
    float* red = sm + 2*IHH*XP + 5*TH*VP;  // [8]

    const int tid  = threadIdx.x;
    const int tile = blockIdx.x;           // 0..31
    const int ic   = blockIdx.y;           // 0..143
    const int ty = tile >> 2, tx = tile & 3;
    const int h0 = ty * TH, w0 = tx * TW;
    const int n  = ic / CHN;

    const float* xp = pred   + ic * NPIX;
    const float* yp = target + ic * NPIX;
    const unsigned char* wb = g_wbonus + n * NPIX;

    float lsum = 0.f;

    // ---- Phase 1: load halo, fold in L1 + weighted-L1 on interior ----
    for (int i = tid; i < IHH * IWW; i += 256) {
        int r = i / IWW, c = i - r * IWW;
        int gh = h0 - 5 + r, gw = w0 - 5 + c;
        float xv = 0.f, yv = 0.f;
        if (gh >= 0 && gh < HH && gw >= 0 && gw < WW) {
            int off = gh * WW + gw;
            xv = xp[off]; yv = yp[off];
        }
        Xp[r * XP + c] = xv;
        Yp[r * XP + c] = yv;
        if (r >= 5 && r < IHH - 5 && c >= 5 && c < IWW - 5) {
            // interior -> gh,gw guaranteed in-image
            float ad    = fabsf(xv - yv);
            float bonus = (float)wb[gh * WW + gw];
            // 10*dssim + 10*ad + 5*(1+bonus)*ad -> (15 + 5*bonus)*ad here
            lsum += (15.f + 5.f * bonus) * ad;
        }
    }
    __syncthreads();

    // ---- Phase V: vertical conv, 8-row register blocking (296 items) ----
    for (int m = tid; m < IWW * 4; m += 256) {
        int col = m % IWW;
        int rg  = m / IWW;                 // rows rg*8 .. rg*8+7
        float amx[8], amy[8], asx[8], asy[8], ae[8];
        #pragma unroll
        for (int o = 0; o < 8; o++) { amx[o]=0.f; amy[o]=0.f; asx[o]=0.f; asy[o]=0.f; ae[o]=0.f; }
        #pragma unroll
        for (int k = 0; k < 18; k++) {
            float xv = Xp[(rg * 8 + k) * XP + col];
            float yv = Yp[(rg * 8 + k) * XP + col];
            float xx = xv * xv, yy = yv * yv, xy = xv * yv;
            #pragma unroll
            for (int o = 0; o < 8; o++) {
                int t = k - o;
                if (t >= 0 && t < 11) {
                    float gg = G[t];
                    amx[o] += gg * xv;  amy[o] += gg * yv;
                    asx[o] += gg * xx;  asy[o] += gg * yy;
                    ae [o] += gg * xy;
                }
            }
        }
        #pragma unroll
        for (int o = 0; o < 8; o++) {
            int row = rg * 8 + o;
            Vb[0*TH*VP + row * VP + col] = amx[o];
            Vb[1*TH*VP + row * VP + col] = amy[o];
            Vb[2*TH*VP + row * VP + col] = asx[o];
            Vb[3*TH*VP + row * VP + col] = asy[o];
            Vb[4*TH*VP + row * VP + col] = ae[o];
        }
    }
    __syncthreads();

    // ---- Phase H: horizontal conv, 8-col blocking (exactly 256 items) ----
    // warp = one 8-column group (cg = tid>>5), lane = output row (tid&31).
    // Bank: (77*row + j) % 32 = (13*row + j) % 32, 13 odd -> conflict-free.
    {
        const int row = tid & 31;
        const int cg  = tid >> 5;
        float amx[8], amy[8], asx[8], asy[8], ae[8];
        #pragma unroll
        for (int o = 0; o < 8; o++) { amx[o]=0.f; amy[o]=0.f; asx[o]=0.f; asy[o]=0.f; ae[o]=0.f; }
        #pragma unroll
        for (int k = 0; k < 18; k++) {
            int j = cg * 8 + k;
            float v0 = Vb[0*TH*VP + row * VP + j];
            float v1 = Vb[1*TH*VP + row * VP + j];
            float v2 = Vb[2*TH*VP + row * VP + j];
            float v3 = Vb[3*TH*VP + row * VP + j];
            float v4 = Vb[4*TH*VP + row * VP + j];
            #pragma unroll
            for (int o = 0; o < 8; o++) {
                int t = k - o;
                if (t >= 0 && t < 11) {
                    float gg = G[t];
                    amx[o] += gg * v0;  amy[o] += gg * v1;
                    asx[o] += gg * v2;  asy[o] += gg * v3;
                    ae [o] += gg * v4;
                }
            }
        }
        const float C1 = 0.01f * 0.01f;
        const float C2 = 0.03f * 0.03f;
        #pragma unroll
        for (int o = 0; o < 8; o++) {
            float mux = amx[o], muy = amy[o];
            float sx  = asx[o] - mux * mux;
            float sy  = asy[o] - muy * muy;
            float sxy = ae [o] - mux * muy;
            float num = (2.f * mux * muy + C1) * (2.f * sxy + C2);
            float den = (mux * mux + muy * muy + C1) * (sx + sy + C2);
            float ssim = num / (den + 1e-8f);
            lsum += 10.f * 0.5f * (1.f - ssim);
        }
    }

    // ---- Reduce: warp shuffles -> 8 partials -> one double atomic ----
    #pragma unroll
    for (int s = 16; s > 0; s >>= 1)
        lsum += __shfl_xor_sync(0xFFFFFFFFu, lsum, s);
    if ((tid & 31) == 0) red[tid >> 5] = lsum;
    __syncthreads();
    if (tid == 0) {
        float t = red[0] + red[1] + red[2] + red[3]
                + red[4] + red[5] + red[6] + red[7];
        atomicAdd(&g_acc, (double)t);
    }
}

__global__ void fin_kernel(float* __restrict__ out) {
    out[0] = (float)(g_acc * (1.0 / (double)(NB * CHN * NPIX)));
}

extern "C" void kernel_launch(void* const* d_in, const int* in_sizes, int n_in,
                              void* d_out, int out_size) {
    (void)in_sizes; (void)n_in; (void)out_size;
    const float* pred   = (const float*)d_in[0];
    const float* target = (const float*)d_in[1];
    const float* lmk    = (const float*)d_in[2];
    float* out = (float*)d_out;

    // Opt-in to >48KB dynamic shared memory (host-side attr; executes at
    // capture time only, zero cost on graph replay).
    cudaFuncSetAttribute(main_kernel, cudaFuncAttributeMaxDynamicSharedMemorySize,
                         SM_BYTES);

    wmap_kernel<<<dim3(HH, NB), WW>>>(lmk);
    main_kernel<<<dim3(32, NIC), 256, SM_BYTES>>>(pred, target);
    fin_kernel<<<1, 1>>>(out);
}

// round 6
// speedup vs baseline: 1.5110x; 1.1109x over previous
#include <cuda_runtime.h>

#define NB   48
#define CHN  3
#define HH   256
#define WW   256
#define NIC  (NB*CHN)
#define NPIX (HH*WW)

#define TH   32
#define TW   64
#define IHH  42           // TH + 10
#define IWW  74           // TW + 10
#define XP   75           // X/Y plane stride (odd bank stride -> conflict-free)
#define VP   77           // V plane stride (77 mod 32 = 13, odd -> conflict-free)
#define NTHR 320
#define NTILE 32
#define NBLK  (NTILE * NIC)   // 4608 main blocks

#define SM_FLOATS (2*IHH*XP + 4*TH*VP + 16)
#define SM_BYTES  (SM_FLOATS * 4)

__device__ double g_acc;
__device__ unsigned int g_count = 0;
__device__ unsigned char g_wbonus[NB * NPIX];   // 3*m0 + 3*m1 + 2*m2 in [0,8]

// Normalized 1D Gaussian, k=11, sigma=1.5
__device__ constexpr float G[11] = {
    0.00102838f, 0.00759876f, 0.03600078f, 0.10936071f, 0.21300554f,
    0.26601172f,
    0.21300554f, 0.10936071f, 0.03600078f, 0.00759876f, 0.00102838f
};

// One block per (row h, image n). Lanes 0..23 evaluate one edge each; only
// edges CROSSING this row are compacted into short per-polygon threshold
// lists (uniform count per row -> uniform loops), so per-pixel work drops
// from 24 compares to ~7 on average. Rows with no crossings early-exit.
__global__ void __launch_bounds__(WW) wmap_kernel(const float* __restrict__ lmk) {
    int h = blockIdx.x;
    int n = blockIdx.y;
    int w = threadIdx.x;

    __shared__ float ethr[24];
    __shared__ int   eflg[24];
    __shared__ float clist[3][12];
    __shared__ int   ccnt[3];
    __shared__ float bxmin[3], bxmax[3];
    __shared__ int   rowok[3];

    if (h == 0 && n == 0 && w == 255) g_acc = 0.0;   // zero for this graph replay

    const float* L = lmk + n * 136;
    float Y = (float)h;

    if (w < 24) {
        int p    = (w < 6) ? 0 : ((w < 12) ? 1 : 2);
        int base = (p == 0) ? 36 : ((p == 1) ? 42 : 48);
        int cnt  = (p == 2) ? 12 : 6;
        int i    = w - ((p == 0) ? 0 : ((p == 1) ? 6 : 12));
        int j    = (i + 1 == cnt) ? 0 : i + 1;
        float x1 = L[2*(base+i)], y1 = L[2*(base+i)+1];
        float x2 = L[2*(base+j)], y2 = L[2*(base+j)+1];
        eflg[w] = ((y1 > Y) != (y2 > Y)) ? 1 : 0;
        ethr[w] = (x2 - x1) * (Y - y1) / (y2 - y1 + 1e-6f) + x1;
    } else if (w < 27) {
        int p    = w - 24;
        int base = (p == 0) ? 36 : ((p == 1) ? 42 : 48);
        int cnt  = (p == 2) ? 12 : 6;
        float mnx = 1e30f, mxx = -1e30f, mny = 1e30f, mxy = -1e30f;
        for (int i = 0; i < cnt; i++) {
            float x = L[2*(base+i)], y = L[2*(base+i)+1];
            mnx = fminf(mnx, x); mxx = fmaxf(mxx, x);
            mny = fminf(mny, y); mxy = fmaxf(mxy, y);
        }
        float fxmin = floorf(mnx), fxmax = floorf(mxx);
        float fymin = floorf(mny), fymax = floorf(mxy);
        bool valid = (fxmin >= 0.f) && (fymin >= 0.f) &&
                     (fxmax < (float)WW) && (fymax < (float)HH);
        rowok[p] = (valid && (Y >= fymin) && (Y < fymax)) ? 1 : 0;
        bxmin[p] = fxmin; bxmax[p] = fxmax;
    }
    __syncthreads();

    if (w < 3) {
        int p = w;
        int s = (p == 0) ? 0 : ((p == 1) ? 6 : 12);
        int cn = (p == 2) ? 12 : 6;
        int c = 0;
        if (rowok[p]) {
            for (int i = 0; i < cn; i++)
                if (eflg[s + i]) clist[p][c++] = ethr[s + i];
        }
        ccnt[p] = c;
    }
    __syncthreads();

    unsigned char* dst = g_wbonus + n * NPIX + h * WW;
    int c0 = ccnt[0], c1 = ccnt[1], c2 = ccnt[2];
    if ((c0 | c1 | c2) == 0) {        // uniform: whole row has bonus 0
        dst[w] = 0;
        return;
    }

    float X = (float)w;
    int bonus = 0;
    {
        int cnt = 0;
        for (int i = 0; i < c0; i++) cnt += (X < clist[0][i]) ? 1 : 0;
        if ((cnt & 1) && (X >= bxmin[0]) && (X < bxmax[0])) bonus += 3;
    }
    {
        int cnt = 0;
        for (int i = 0; i < c1; i++) cnt += (X < clist[1][i]) ? 1 : 0;
        if ((cnt & 1) && (X >= bxmin[1]) && (X < bxmax[1])) bonus += 3;
    }
    {
        int cnt = 0;
        for (int i = 0; i < c2; i++) cnt += (X < clist[2][i]) ? 1 : 0;
        if ((cnt & 1) && (X >= bxmin[2]) && (X < bxmax[2])) bonus += 2;
    }
    dst[w] = (unsigned char)bonus;
}

// Fused main: 32x64 tile, 320 threads. Phase1 loads halo + folds in L1 terms.
// PhaseV: vertical 11-tap conv of 4 fields (x, y, x^2+y^2, x*y), 8-row
// register blocking -> 296 items in ONE wave. PhaseH: horizontal conv
// (8-col blocking, 256 items) + dssim. Last block writes the final scalar.
__global__ void __launch_bounds__(NTHR, 3) main_kernel(const float* __restrict__ pred,
                                                       const float* __restrict__ target,
                                                       float* __restrict__ out) {
    extern __shared__ float sm[];
    float* Xp  = sm;                       // [IHH][XP]
    float* Yp  = sm +   IHH*XP;            // [IHH][XP]
    float* Vb  = sm + 2*IHH*XP;            // 4 planes [TH][VP]
    float* red = sm + 2*IHH*XP + 4*TH*VP;  // [10]

    const int tid  = threadIdx.x;
    const int tile = blockIdx.x;           // 0..31
    const int ic   = blockIdx.y;           // 0..143
    const int ty = tile >> 2, tx = tile & 3;
    const int h0 = ty * TH, w0 = tx * TW;
    const int n  = ic / CHN;

    const float* xp = pred   + ic * NPIX;
    const float* yp = target + ic * NPIX;
    const unsigned char* wb = g_wbonus + n * NPIX;

    float lsum = 0.f;

    // ---- Phase 1: load halo, fold in L1 + weighted-L1 on interior ----
    for (int i = tid; i < IHH * IWW; i += NTHR) {
        int r = i / IWW, c = i - r * IWW;
        int gh = h0 - 5 + r, gw = w0 - 5 + c;
        float xv = 0.f, yv = 0.f;
        if (gh >= 0 && gh < HH && gw >= 0 && gw < WW) {
            int off = gh * WW + gw;
            xv = xp[off]; yv = yp[off];
        }
        Xp[r * XP + c] = xv;
        Yp[r * XP + c] = yv;
        if (r >= 5 && r < IHH - 5 && c >= 5 && c < IWW - 5) {
            float ad    = fabsf(xv - yv);
            float bonus = (float)wb[gh * WW + gw];
            // 10*dssim + 10*ad + 5*(1+bonus)*ad -> (15 + 5*bonus)*ad here
            lsum += (15.f + 5.f * bonus) * ad;
        }
    }
    __syncthreads();

    // ---- Phase V: vertical conv of 4 fields, 8-row blocking, ONE wave ----
    if (tid < IWW * 4) {
        int col = tid % IWW;
        int rg  = tid / IWW;               // rows rg*8 .. rg*8+7
        float amx[8], amy[8], ass[8], axy[8];
        #pragma unroll
        for (int o = 0; o < 8; o++) { amx[o]=0.f; amy[o]=0.f; ass[o]=0.f; axy[o]=0.f; }
        #pragma unroll
        for (int k = 0; k < 18; k++) {
            float xv = Xp[(rg * 8 + k) * XP + col];
            float yv = Yp[(rg * 8 + k) * XP + col];
            float ss = fmaf(xv, xv, yv * yv);   // x^2 + y^2
            float xy = xv * yv;
            #pragma unroll
            for (int o = 0; o < 8; o++) {
                int t = k - o;
                if (t >= 0 && t < 11) {
                    float gg = G[t];
                    amx[o] += gg * xv;  amy[o] += gg * yv;
                    ass[o] += gg * ss;  axy[o] += gg * xy;
                }
            }
        }
        #pragma unroll
        for (int o = 0; o < 8; o++) {
            int row = rg * 8 + o;
            Vb[0*TH*VP + row * VP + col] = amx[o];
            Vb[1*TH*VP + row * VP + col] = amy[o];
            Vb[2*TH*VP + row * VP + col] = ass[o];
            Vb[3*TH*VP + row * VP + col] = axy[o];
        }
    }
    __syncthreads();

    // ---- Phase H: horizontal conv, 8-col blocking (256 items) + dssim ----
    // warp = one 8-column group, lane = output row. Bank stride
    // (77*row + j) % 32 = (13*row + j) % 32, 13 odd -> conflict-free.
    if (tid < 256) {
        const int row = tid & 31;
        const int cg  = tid >> 5;
        float amx[8], amy[8], ass[8], axy[8];
        #pragma unroll
        for (int o = 0; o < 8; o++) { amx[o]=0.f; amy[o]=0.f; ass[o]=0.f; axy[o]=0.f; }
        #pragma unroll
        for (int k = 0; k < 18; k++) {
            int j = cg * 8 + k;
            float v0 = Vb[0*TH*VP + row * VP + j];
            float v1 = Vb[1*TH*VP + row * VP + j];
            float v2 = Vb[2*TH*VP + row * VP + j];
            float v3 = Vb[3*TH*VP + row * VP + j];
            #pragma unroll
            for (int o = 0; o < 8; o++) {
                int t = k - o;
                if (t >= 0 && t < 11) {
                    float gg = G[t];
                    amx[o] += gg * v0;  amy[o] += gg * v1;
                    ass[o] += gg * v2;  axy[o] += gg * v3;
                }
            }
        }
        const float C1 = 0.01f * 0.01f;
        const float C2 = 0.03f * 0.03f;
        #pragma unroll
        for (int o = 0; o < 8; o++) {
            float mux = amx[o], muy = amy[o];
            float sxy  = axy[o] - mux * muy;
            float ssum = ass[o] - mux * mux - muy * muy;  // sigma_x + sigma_y
            float num = (2.f * mux * muy + C1) * (2.f * sxy + C2);
            float den = (mux * mux + muy * muy + C1) * (ssum + C2);
            float ssim = num / (den + 1e-8f);
            lsum += 10.f * 0.5f * (1.f - ssim);
        }
    }

    // ---- Reduce: warp shuffles -> 10 partials -> one double atomic ----
    #pragma unroll
    for (int s = 16; s > 0; s >>= 1)
        lsum += __shfl_xor_sync(0xFFFFFFFFu, lsum, s);
    if ((tid & 31) == 0) red[tid >> 5] = lsum;
    __syncthreads();
    if (tid == 0) {
        float t = 0.f;
        #pragma unroll
        for (int i = 0; i < NTHR / 32; i++) t += red[i];
        atomicAdd(&g_acc, (double)t);
        __threadfence();
        unsigned int old = atomicAdd(&g_count, 1u);
        if (old == NBLK - 1) {
            double v = atomicAdd(&g_acc, 0.0);   // coherent read of final sum
            out[0] = (float)(v * (1.0 / (double)(NB * CHN * NPIX)));
            g_count = 0;                          // reset for next graph replay
        }
    }
}

extern "C" void kernel_launch(void* const* d_in, const int* in_sizes, int n_in,
                              void* d_out, int out_size) {
    (void)in_sizes; (void)n_in; (void)out_size;
    const float* pred   = (const float*)d_in[0];
    const float* target = (const float*)d_in[1];
    const float* lmk    = (const float*)d_in[2];
    float* out = (float*)d_out;

    cudaFuncSetAttribute(main_kernel, cudaFuncAttributeMaxDynamicSharedMemorySize,
                         SM_BYTES);

    wmap_kernel<<<dim3(HH, NB), WW>>>(lmk);
    main_kernel<<<dim3(NTILE, NIC), NTHR, SM_BYTES>>>(pred, target, out);
}

// round 7
// speedup vs baseline: 1.7227x; 1.1401x over previous
#include <cuda_runtime.h>

#define NB   48
#define CHN  3
#define HH   256
#define WW   256
#define NIC  (NB*CHN)
#define NPIX (HH*WW)

#define TH   32
#define TW   64
#define IHH  42           // TH + 10
#define IWW  74           // TW + 10
#define XP2  75           // float2 plane stride (odd -> conflict-free LDS.64)
#define VP4  75           // float4 plane stride (12r mod 32 distinct -> conflict-free LDS.128)
#define NTHR 320
#define NTILE 32
#define NBLK  (NTILE * NIC)   // 4608 main blocks

#define SM_FLOATS (2*IHH*XP2 + 4*TH*VP4 + 16)
#define SM_BYTES  (SM_FLOATS * 4)

__device__ double g_acc;
__device__ unsigned int g_count = 0;
__device__ unsigned char g_wbonus[NB * NPIX];   // 3*m0 + 3*m1 + 2*m2 in [0,8]

// Normalized 1D Gaussian, k=11, sigma=1.5
__device__ constexpr float G[11] = {
    0.00102838f, 0.00759876f, 0.03600078f, 0.10936071f, 0.21300554f,
    0.26601172f,
    0.21300554f, 0.10936071f, 0.03600078f, 0.00759876f, 0.00102838f
};

// 8 rows per block (amortize per-block fixed cost). 192 threads evaluate
// (row, edge) pairs; 24 threads compact crossing thresholds per (row, poly);
// then 8 uniform per-row pixel passes (~7 compares avg instead of 24).
__global__ void __launch_bounds__(WW) wmap_kernel(const float* __restrict__ lmk) {
    const int rbase = blockIdx.x * 8;
    const int n     = blockIdx.y;
    const int tid   = threadIdx.x;

    __shared__ float ethr[8][24];
    __shared__ int   eflg[8][24];
    __shared__ float clist[8][3][12];
    __shared__ int   ccnt[8][3];
    __shared__ float bxmin[3], bxmax[3], fymn[3], fymx[3];
    __shared__ int   pval[3];

    if (rbase == 0 && n == 0 && tid == 255) g_acc = 0.0;  // zero per replay

    const float* L = lmk + n * 136;

    if (tid < 192) {
        int rr = tid / 24, e = tid % 24;
        float Y = (float)(rbase + rr);
        int p    = (e < 6) ? 0 : ((e < 12) ? 1 : 2);
        int base = (p == 0) ? 36 : ((p == 1) ? 42 : 48);
        int cnt  = (p == 2) ? 12 : 6;
        int i    = e - ((p == 0) ? 0 : ((p == 1) ? 6 : 12));
        int j    = (i + 1 == cnt) ? 0 : i + 1;
        float x1 = L[2*(base+i)], y1 = L[2*(base+i)+1];
        float x2 = L[2*(base+j)], y2 = L[2*(base+j)+1];
        eflg[rr][e] = ((y1 > Y) != (y2 > Y)) ? 1 : 0;
        ethr[rr][e] = (x2 - x1) * (Y - y1) / (y2 - y1 + 1e-6f) + x1;
    } else if (tid < 195) {
        int p    = tid - 192;
        int base = (p == 0) ? 36 : ((p == 1) ? 42 : 48);
        int cnt  = (p == 2) ? 12 : 6;
        float mnx = 1e30f, mxx = -1e30f, mny = 1e30f, mxy = -1e30f;
        for (int i = 0; i < cnt; i++) {
            float x = L[2*(base+i)], y = L[2*(base+i)+1];
            mnx = fminf(mnx, x); mxx = fmaxf(mxx, x);
            mny = fminf(mny, y); mxy = fmaxf(mxy, y);
        }
        float fxmin = floorf(mnx), fxmax = floorf(mxx);
        fymn[p] = floorf(mny);  fymx[p] = floorf(mxy);
        pval[p] = ((fxmin >= 0.f) && (fymn[p] >= 0.f) &&
                   (fxmax < (float)WW) && (fymx[p] < (float)HH)) ? 1 : 0;
        bxmin[p] = fxmin; bxmax[p] = fxmax;
    }
    __syncthreads();

    if (tid < 24) {
        int rr = tid / 3, p = tid % 3;
        float Y = (float)(rbase + rr);
        int s  = (p == 0) ? 0 : ((p == 1) ? 6 : 12);
        int cn = (p == 2) ? 12 : 6;
        int c = 0;
        if (pval[p] && (Y >= fymn[p]) && (Y < fymx[p])) {
            for (int i = 0; i < cn; i++)
                if (eflg[rr][s + i]) clist[rr][p][c++] = ethr[rr][s + i];
        }
        ccnt[rr][p] = c;
    }
    __syncthreads();

    unsigned char* dst = g_wbonus + n * NPIX + rbase * WW;
    float X = (float)tid;
    #pragma unroll
    for (int r = 0; r < 8; r++) {
        int c0 = ccnt[r][0], c1 = ccnt[r][1], c2 = ccnt[r][2];
        int bonus = 0;
        if ((c0 | c1 | c2) != 0) {
            int cnt = 0;
            for (int i = 0; i < c0; i++) cnt += (X < clist[r][0][i]) ? 1 : 0;
            if ((cnt & 1) && (X >= bxmin[0]) && (X < bxmax[0])) bonus += 3;
            cnt = 0;
            for (int i = 0; i < c1; i++) cnt += (X < clist[r][1][i]) ? 1 : 0;
            if ((cnt & 1) && (X >= bxmin[1]) && (X < bxmax[1])) bonus += 3;
            cnt = 0;
            for (int i = 0; i < c2; i++) cnt += (X < clist[r][2][i]) ? 1 : 0;
            if ((cnt & 1) && (X >= bxmin[2]) && (X < bxmax[2])) bonus += 2;
        }
        dst[r * WW + tid] = (unsigned char)bonus;
    }
}

// Fused main, fully vectorized SMEM: (x,y) as float2, the 4 conv fields
// (mu_x, mu_y, x^2+y^2, x*y) as one float4 per (row,col).
__global__ void __launch_bounds__(NTHR, 3) main_kernel(const float* __restrict__ pred,
                                                       const float* __restrict__ target,
                                                       float* __restrict__ out) {
    extern __shared__ float sm[];
    float2* sXY = (float2*)sm;                    // [IHH][XP2]
    float4* Vb  = (float4*)(sm + 2*IHH*XP2);      // [TH][VP4]
    float*  red = sm + 2*IHH*XP2 + 4*TH*VP4;      // [10]

    const int tid  = threadIdx.x;
    const int tile = blockIdx.x;           // 0..31
    const int ic   = blockIdx.y;           // 0..143
    const int ty = tile >> 2, tx = tile & 3;
    const int h0 = ty * TH, w0 = tx * TW;
    const int n  = ic / CHN;

    const float* xp = pred   + ic * NPIX;
    const float* yp = target + ic * NPIX;
    const unsigned char* wb = g_wbonus + n * NPIX;

    float lsum = 0.f;

    // ---- Phase 1: load halo (float2 STS.64), fold in L1 terms ----
    for (int i = tid; i < IHH * IWW; i += NTHR) {
        int r = i / IWW, c = i - r * IWW;
        int gh = h0 - 5 + r, gw = w0 - 5 + c;
        float xv = 0.f, yv = 0.f;
        if (gh >= 0 && gh < HH && gw >= 0 && gw < WW) {
            int off = gh * WW + gw;
            xv = xp[off]; yv = yp[off];
        }
        sXY[r * XP2 + c] = make_float2(xv, yv);
        if (r >= 5 && r < IHH - 5 && c >= 5 && c < IWW - 5) {
            float ad    = fabsf(xv - yv);
            float bonus = (float)wb[gh * WW + gw];
            // 10*dssim + 10*ad + 5*(1+bonus)*ad -> (15 + 5*bonus)*ad here
            lsum += (15.f + 5.f * bonus) * ad;
        }
    }
    __syncthreads();

    // ---- Phase V: vertical conv of 4 fields, 8-row blocking, ONE wave ----
    if (tid < IWW * 4) {
        int col = tid % IWW;
        int rg  = tid / IWW;               // rows rg*8 .. rg*8+7
        float4 a[8];
        #pragma unroll
        for (int o = 0; o < 8; o++) a[o] = make_float4(0.f, 0.f, 0.f, 0.f);
        #pragma unroll
        for (int k = 0; k < 18; k++) {
            float2 p  = sXY[(rg * 8 + k) * XP2 + col];
            float  ss = fmaf(p.x, p.x, p.y * p.y);
            float  xy = p.x * p.y;
            #pragma unroll
            for (int o = 0; o < 8; o++) {
                int t = k - o;
                if (t >= 0 && t < 11) {
                    float gg = G[t];
                    a[o].x = fmaf(gg, p.x, a[o].x);
                    a[o].y = fmaf(gg, p.y, a[o].y);
                    a[o].z = fmaf(gg, ss,  a[o].z);
                    a[o].w = fmaf(gg, xy,  a[o].w);
                }
            }
        }
        #pragma unroll
        for (int o = 0; o < 8; o++)
            Vb[(rg * 8 + o) * VP4 + col] = a[o];   // STS.128
    }
    __syncthreads();

    // ---- Phase H: horizontal conv (LDS.128), 8-col blocking + dssim ----
    // warp = one 8-col group, lane = output row. float4 bank group
    // = 12*row mod 32 -> distinct within each 8-lane phase: conflict-free.
    if (tid < 256) {
        const int row = tid & 31;
        const int cg  = tid >> 5;
        const float4* vrow = Vb + row * VP4 + cg * 8;
        float4 a[8];
        #pragma unroll
        for (int o = 0; o < 8; o++) a[o] = make_float4(0.f, 0.f, 0.f, 0.f);
        #pragma unroll
        for (int k = 0; k < 18; k++) {
            float4 v = vrow[k];
            #pragma unroll
            for (int o = 0; o < 8; o++) {
                int t = k - o;
                if (t >= 0 && t < 11) {
                    float gg = G[t];
                    a[o].x = fmaf(gg, v.x, a[o].x);
                    a[o].y = fmaf(gg, v.y, a[o].y);
                    a[o].z = fmaf(gg, v.z, a[o].z);
                    a[o].w = fmaf(gg, v.w, a[o].w);
                }
            }
        }
        const float C1 = 0.01f * 0.01f;
        const float C2 = 0.03f * 0.03f;
        #pragma unroll
        for (int o = 0; o < 8; o++) {
            float mux = a[o].x, muy = a[o].y;
            float sxy  = a[o].w - mux * muy;
            float ssum = a[o].z - mux * mux - muy * muy;  // sigma_x + sigma_y
            float num = (2.f * mux * muy + C1) * (2.f * sxy + C2);
            float den = (mux * mux + muy * muy + C1) * (ssum + C2);
            float ssim = num / (den + 1e-8f);
            lsum += 10.f * 0.5f * (1.f - ssim);
        }
    }

    // ---- Reduce: warp shuffles -> 10 partials -> one double atomic ----
    #pragma unroll
    for (int s = 16; s > 0; s >>= 1)
        lsum += __shfl_xor_sync(0xFFFFFFFFu, lsum, s);
    if ((tid & 31) == 0) red[tid >> 5] = lsum;
    __syncthreads();
    if (tid == 0) {
        float t = 0.f;
        #pragma unroll
        for (int i = 0; i < NTHR / 32; i++) t += red[i];
        atomicAdd(&g_acc, (double)t);
        __threadfence();
        unsigned int old = atomicAdd(&g_count, 1u);
        if (old == NBLK - 1) {
            double v = atomicAdd(&g_acc, 0.0);   // coherent read of final sum
            out[0] = (float)(v * (1.0 / (double)(NB * CHN * NPIX)));
            g_count = 0;                          // reset for next graph replay
        }
    }
}

extern "C" void kernel_launch(void* const* d_in, const int* in_sizes, int n_in,
                              void* d_out, int out_size) {
    (void)in_sizes; (void)n_in; (void)out_size;
    const float* pred   = (const float*)d_in[0];
    const float* target = (const float*)d_in[1];
    const float* lmk    = (const float*)d_in[2];
    float* out = (float*)d_out;

    cudaFuncSetAttribute(main_kernel, cudaFuncAttributeMaxDynamicSharedMemorySize,
                         SM_BYTES);

    wmap_kernel<<<dim3(HH / 8, NB), WW>>>(lmk);
    main_kernel<<<dim3(NTILE, NIC), NTHR, SM_BYTES>>>(pred, target, out);
}

// round 8
// speedup vs baseline: 2.2697x; 1.3175x over previous
#include <cuda_runtime.h>

#define NB   48
#define CHN  3
#define HH   256
#define WW   256
#define NIC  (NB*CHN)
#define NPIX (HH*WW)

#define TH   32
#define TW   64
#define IHH  42           // TH + 10
#define IWW  74           // TW + 10
#define XP2  75           // float2 plane stride (odd -> conflict-free LDS.64)
#define VP4  75           // float4 plane stride (3r mod 8 distinct -> conflict-free LDS.128)
#define NTHR 320
#define NTILE 32
#define NWORK (NTILE * NIC)   // 4608 tiles
#define GRID  444             // 3 blocks/SM * 148 SMs -> single wave, persistent

#define SM_FLOATS (2*IHH*XP2 + 4*TH*VP4 + 16)
#define SM_BYTES  (SM_FLOATS * 4)

__device__ double g_acc;
__device__ unsigned int g_count = 0;
__device__ unsigned char g_wbonus[NB * NPIX];   // 3*m0 + 3*m1 + 2*m2 in [0,8]

// Normalized 1D Gaussian, k=11, sigma=1.5
__device__ constexpr float G[11] = {
    0.00102838f, 0.00759876f, 0.03600078f, 0.10936071f, 0.21300554f,
    0.26601172f,
    0.21300554f, 0.10936071f, 0.03600078f, 0.00759876f, 0.00102838f
};

// 8 rows per block. 192 threads evaluate (row, edge) pairs; 24 compact
// crossing thresholds; 8 uniform per-row pixel passes.
__global__ void __launch_bounds__(WW) wmap_kernel(const float* __restrict__ lmk) {
    const int rbase = blockIdx.x * 8;
    const int n     = blockIdx.y;
    const int tid   = threadIdx.x;

    __shared__ float ethr[8][24];
    __shared__ int   eflg[8][24];
    __shared__ float clist[8][3][12];
    __shared__ int   ccnt[8][3];
    __shared__ float bxmin[3], bxmax[3], fymn[3], fymx[3];
    __shared__ int   pval[3];

    if (rbase == 0 && n == 0 && tid == 255) g_acc = 0.0;  // zero per replay

    const float* L = lmk + n * 136;

    if (tid < 192) {
        int rr = tid / 24, e = tid % 24;
        float Y = (float)(rbase + rr);
        int p    = (e < 6) ? 0 : ((e < 12) ? 1 : 2);
        int base = (p == 0) ? 36 : ((p == 1) ? 42 : 48);
        int cnt  = (p == 2) ? 12 : 6;
        int i    = e - ((p == 0) ? 0 : ((p == 1) ? 6 : 12));
        int j    = (i + 1 == cnt) ? 0 : i + 1;
        float x1 = L[2*(base+i)], y1 = L[2*(base+i)+1];
        float x2 = L[2*(base+j)], y2 = L[2*(base+j)+1];
        eflg[rr][e] = ((y1 > Y) != (y2 > Y)) ? 1 : 0;
        ethr[rr][e] = (x2 - x1) * (Y - y1) / (y2 - y1 + 1e-6f) + x1;
    } else if (tid < 195) {
        int p    = tid - 192;
        int base = (p == 0) ? 36 : ((p == 1) ? 42 : 48);
        int cnt  = (p == 2) ? 12 : 6;
        float mnx = 1e30f, mxx = -1e30f, mny = 1e30f, mxy = -1e30f;
        for (int i = 0; i < cnt; i++) {
            float x = L[2*(base+i)], y = L[2*(base+i)+1];
            mnx = fminf(mnx, x); mxx = fmaxf(mxx, x);
            mny = fminf(mny, y); mxy = fmaxf(mxy, y);
        }
        float fxmin = floorf(mnx), fxmax = floorf(mxx);
        fymn[p] = floorf(mny);  fymx[p] = floorf(mxy);
        pval[p] = ((fxmin >= 0.f) && (fymn[p] >= 0.f) &&
                   (fxmax < (float)WW) && (fymx[p] < (float)HH)) ? 1 : 0;
        bxmin[p] = fxmin; bxmax[p] = fxmax;
    }
    __syncthreads();

    if (tid < 24) {
        int rr = tid / 3, p = tid % 3;
        float Y = (float)(rbase + rr);
        int s  = (p == 0) ? 0 : ((p == 1) ? 6 : 12);
        int cn = (p == 2) ? 12 : 6;
        int c = 0;
        if (pval[p] && (Y >= fymn[p]) && (Y < fymx[p])) {
            for (int i = 0; i < cn; i++)
                if (eflg[rr][s + i]) clist[rr][p][c++] = ethr[rr][s + i];
        }
        ccnt[rr][p] = c;
    }
    __syncthreads();

    unsigned char* dst = g_wbonus + n * NPIX + rbase * WW;
    float X = (float)tid;
    #pragma unroll
    for (int r = 0; r < 8; r++) {
        int c0 = ccnt[r][0], c1 = ccnt[r][1], c2 = ccnt[r][2];
        int bonus = 0;
        if ((c0 | c1 | c2) != 0) {
            int cnt = 0;
            for (int i = 0; i < c0; i++) cnt += (X < clist[r][0][i]) ? 1 : 0;
            if ((cnt & 1) && (X >= bxmin[0]) && (X < bxmax[0])) bonus += 3;
            cnt = 0;
            for (int i = 0; i < c1; i++) cnt += (X < clist[r][1][i]) ? 1 : 0;
            if ((cnt & 1) && (X >= bxmin[1]) && (X < bxmax[1])) bonus += 3;
            cnt = 0;
            for (int i = 0; i < c2; i++) cnt += (X < clist[r][2][i]) ? 1 : 0;
            if ((cnt & 1) && (X >= bxmin[2]) && (X < bxmax[2])) bonus += 2;
        }
        dst[r * WW + tid] = (unsigned char)bonus;
    }
}

// Persistent fused main: 444 blocks loop over 4608 tiles. Per tile:
// phase1 halo load (structured r/c, minimal ALU) + L1 fold, phaseV vertical
// conv of 4 fields (float4 planes), phaseH horizontal conv + dssim.
__global__ void __launch_bounds__(NTHR, 3) main_kernel(const float* __restrict__ pred,
                                                       const float* __restrict__ target,
                                                       float* __restrict__ out) {
    extern __shared__ float sm[];
    float2* sXY = (float2*)sm;                    // [IHH][XP2]
    float4* Vb  = (float4*)(sm + 2*IHH*XP2);      // [TH][VP4]
    float*  red = sm + 2*IHH*XP2 + 4*TH*VP4;      // [10]

    const int tid = threadIdx.x;

    // Phase-1 fixed decomposition: column c1 (once), row base r1.
    const int  c1    = tid % 80;            // column in halo if < IWW
    const int  r1    = tid / 80;            // row base, rows r1 + 4*it
    const bool cok   = (c1 < IWW);
    const bool cint  = (c1 >= 5) && (c1 < IWW - 5);

    // Phase-V decomposition (once)
    const int  vcol  = tid % IWW;
    const int  vrg   = tid / IWW;           // 0..3 for tid < 296
    // Phase-H decomposition (once)
    const int  hrow  = tid & 31;
    const int  hcg   = tid >> 5;

    float lsum = 0.f;

    for (int work = blockIdx.x; work < NWORK; work += GRID) {
        const int tile = work & (NTILE - 1);
        const int ic   = work >> 5;
        const int ty = tile >> 2, tx = tile & 3;
        const int h0 = ty * TH, w0 = tx * TW;
        const int n  = ic / CHN;

        const float* xp = pred   + ic * NPIX;
        const float* yp = target + ic * NPIX;
        const unsigned char* wb = g_wbonus + n * NPIX;

        __syncthreads();   // prev iteration fully done with SMEM

        // ---- Phase 1: halo load + L1/weighted-L1 fold ----
        if (cok) {
            const int  gw   = w0 - 5 + c1;
            const bool gwok = (gw >= 0) && (gw < WW);
            #pragma unroll
            for (int it = 0; it < 11; it++) {
                int r = r1 + 4 * it;
                if (r1 < 2 || it < 10) {            // r < IHH
                    int gh = h0 - 5 + r;
                    bool ok = gwok && (gh >= 0) && (gh < HH);
                    int  off = gh * WW + gw;
                    float xv = 0.f, yv = 0.f;
                    if (ok) { xv = xp[off]; yv = yp[off]; }
                    sXY[r * XP2 + c1] = make_float2(xv, yv);
                    if (cint && r >= 5 && r < IHH - 5) {
                        float ad    = fabsf(xv - yv);
                        float bonus = (float)wb[off];
                        // (15 + 5*bonus)*ad  == 10*ad + 5*(1+bonus)*ad
                        lsum += (15.f + 5.f * bonus) * ad;
                    }
                }
            }
        }
        __syncthreads();

        // ---- Phase V: vertical conv of 4 fields, 8-row blocking ----
        if (tid < IWW * 4) {
            float4 a[8];
            #pragma unroll
            for (int o = 0; o < 8; o++) a[o] = make_float4(0.f, 0.f, 0.f, 0.f);
            #pragma unroll
            for (int k = 0; k < 18; k++) {
                float2 p  = sXY[(vrg * 8 + k) * XP2 + vcol];
                float  ss = fmaf(p.x, p.x, p.y * p.y);
                float  xy = p.x * p.y;
                #pragma unroll
                for (int o = 0; o < 8; o++) {
                    int t = k - o;
                    if (t >= 0 && t < 11) {
                        float gg = G[t];
                        a[o].x = fmaf(gg, p.x, a[o].x);
                        a[o].y = fmaf(gg, p.y, a[o].y);
                        a[o].z = fmaf(gg, ss,  a[o].z);
                        a[o].w = fmaf(gg, xy,  a[o].w);
                    }
                }
            }
            #pragma unroll
            for (int o = 0; o < 8; o++)
                Vb[(vrg * 8 + o) * VP4 + vcol] = a[o];   // STS.128
        }
        __syncthreads();

        // ---- Phase H: horizontal conv (LDS.128) + dssim ----
        if (tid < 256) {
            const float4* vrow = Vb + hrow * VP4 + hcg * 8;
            float4 a[8];
            #pragma unroll
            for (int o = 0; o < 8; o++) a[o] = make_float4(0.f, 0.f, 0.f, 0.f);
            #pragma unroll
            for (int k = 0; k < 18; k++) {
                float4 v = vrow[k];
                #pragma unroll
                for (int o = 0; o < 8; o++) {
                    int t = k - o;
                    if (t >= 0 && t < 11) {
                        float gg = G[t];
                        a[o].x = fmaf(gg, v.x, a[o].x);
                        a[o].y = fmaf(gg, v.y, a[o].y);
                        a[o].z = fmaf(gg, v.z, a[o].z);
                        a[o].w = fmaf(gg, v.w, a[o].w);
                    }
                }
            }
            const float C1 = 0.01f * 0.01f;
            const float C2 = 0.03f * 0.03f;
            #pragma unroll
            for (int o = 0; o < 8; o++) {
                float mux = a[o].x, muy = a[o].y;
                float sxy  = a[o].w - mux * muy;
                float ssum = a[o].z - mux * mux - muy * muy;  // sigma_x+sigma_y
                float num = (2.f * mux * muy + C1) * (2.f * sxy + C2);
                float den = (mux * mux + muy * muy + C1) * (ssum + C2);
                float ssim = num / (den + 1e-8f);
                lsum += 10.f * 0.5f * (1.f - ssim);
            }
        }
    }

    // ---- Final reduce (once per block): shuffles -> partials -> atomic ----
    #pragma unroll
    for (int s = 16; s > 0; s >>= 1)
        lsum += __shfl_xor_sync(0xFFFFFFFFu, lsum, s);
    if ((tid & 31) == 0) red[tid >> 5] = lsum;
    __syncthreads();
    if (tid == 0) {
        float t = 0.f;
        #pragma unroll
        for (int i = 0; i < NTHR / 32; i++) t += red[i];
        atomicAdd(&g_acc, (double)t);
        __threadfence();
        unsigned int old = atomicAdd(&g_count, 1u);
        if (old == GRID - 1) {
            double v = atomicAdd(&g_acc, 0.0);   // coherent read of final sum
            out[0] = (float)(v * (1.0 / (double)(NB * CHN * NPIX)));
            g_count = 0;                          // reset for next graph replay
        }
    }
}

extern "C" void kernel_launch(void* const* d_in, const int* in_sizes, int n_in,
                              void* d_out, int out_size) {
    (void)in_sizes; (void)n_in; (void)out_size;
    const float* pred   = (const float*)d_in[0];
    const float* target = (const float*)d_in[1];
    const float* lmk    = (const float*)d_in[2];
    float* out = (float*)d_out;

    cudaFuncSetAttribute(main_kernel, cudaFuncAttributeMaxDynamicSharedMemorySize,
                         SM_BYTES);

    wmap_kernel<<<dim3(HH / 8, NB), WW>>>(lmk);
    main_kernel<<<GRID, NTHR, SM_BYTES>>>(pred, target, out);
}